// round 14
// baseline (speedup 1.0000x reference)
#include <cuda_runtime.h>
#include <stdint.h>
#include <stddef.h>

// Problem constants
#define DRUGN   100000
#define DISN    100000
#define NRD     200000
#define HIDN    64
#define EDG_RR  1600000
#define EDG_DD  1600000
#define EDG_RD  3200000
#define E_TOT   6400000
#define HBITS   6400000u     // flat-index offset of dis rows (100000*64)
#define EPSF    0.1f

// Output packing (float32), tuple order:
// drugE, disE, drugAll, disAll, rd_drug, rd_dis, meta_reg_loss, rd_stack
// NOTE: OFF_RDSTACK is ODD -> rd_stack is only 4-byte aligned; never use
// vector (float2/float4) accesses on the rds pointer.
static const size_t OFF_DRUGE   = 0;
static const size_t OFF_DISE    = 6400000;
static const size_t OFF_DRUGALL = 12800000;
static const size_t OFF_DISALL  = 19200000;
static const size_t OFF_RDDRUG  = 25600000;
static const size_t OFF_RDDIS   = 32000000;
static const size_t OFF_LOSS    = 38400000;
static const size_t OFF_RDSTACK = 38400001;

// Scratch (static device arrays: no runtime allocation allowed)
__device__ float g_G   [(size_t)NRD * HIDN];  // gated init (rr0 | dd0)
__device__ float g_curA[(size_t)NRD * HIDN];  // cur ping
__device__ float g_curB[(size_t)NRD * HIDN];  // cur pong
__device__ float g_deg[800000];               // degree sums: 6 slices
__device__ int2  g_csr[E_TOT];                // packed (col, w) per edge, global CSR order
__device__ int   g_cnt[400000];               // row counts: rr|dd|rd (contiguous)
__device__ int   g_rptr[400001];              // GLOBAL row pointers (exclusive scan of cnt)
__device__ int   g_cursor[400001];            // scatter cursors
__device__ int   g_bsum[256];                 // per-block sums for multi-block scan

// count/rptr slices (global scan makes edge offsets global automatically)
#define CNT_RR 0
#define CNT_DD 100000
#define CNT_RD 200000
// deg slices
#define DRR_R 0
#define DRR_C 100000
#define DDD_R 200000
#define DDD_C 300000
#define DRD_R 400000
#define DRD_C 600000

#define SCAN_N    400000
#define SCAN_BLK  2048
#define SCAN_NB   ((SCAN_N + SCAN_BLK - 1) / SCAN_BLK)   // 196

// ---------------- threefry2x32 (bit-exact JAX core) ----------------
#define TFROUND(x0,x1,r) { x0 += x1; x1 = __funnelshift_l(x1,x1,r); x1 ^= x0; }

__device__ __forceinline__ void tf2x32(uint32_t k0, uint32_t k1, uint32_t &x0, uint32_t &x1) {
    uint32_t k2 = k0 ^ k1 ^ 0x1BD11BDAu;
    x0 += k0; x1 += k1;
    TFROUND(x0,x1,13) TFROUND(x0,x1,15) TFROUND(x0,x1,26) TFROUND(x0,x1,6)
    x0 += k1; x1 += k2 + 1u;
    TFROUND(x0,x1,17) TFROUND(x0,x1,29) TFROUND(x0,x1,16) TFROUND(x0,x1,24)
    x0 += k2; x1 += k0 + 2u;
    TFROUND(x0,x1,13) TFROUND(x0,x1,15) TFROUND(x0,x1,26) TFROUND(x0,x1,6)
    x0 += k0; x1 += k1 + 3u;
    TFROUND(x0,x1,17) TFROUND(x0,x1,29) TFROUND(x0,x1,16) TFROUND(x0,x1,24)
    x0 += k1; x1 += k2 + 4u;
    TFROUND(x0,x1,13) TFROUND(x0,x1,15) TFROUND(x0,x1,26) TFROUND(x0,x1,6)
    x0 += k2; x1 += k0 + 5u;
}

// Partitionable-threefry random bits: counter (0, f); bits = y0 ^ y1.
__device__ __forceinline__ uint32_t tf_bits32(uint32_t k0, uint32_t k1, uint32_t f) {
    uint32_t x0 = 0u, x1 = f;
    tf2x32(k0, k1, x0, x1);
    return x0 ^ x1;
}

__device__ __forceinline__ float u01(uint32_t b) {
    return __uint_as_float((b >> 9) | 0x3f800000u) - 1.0f;
}
__device__ __forceinline__ float fsgn(float x) {
    return (x > 0.f) ? 1.f : ((x < 0.f) ? -1.f : 0.f);
}

// ---------------- init: gated GEMM + buffer init + scratch zeroing ----------------
__global__ void init_kernel(const float* __restrict__ de, const float* __restrict__ se,
                            const float* __restrict__ Wr, const float* __restrict__ br,
                            const float* __restrict__ Wd, const float* __restrict__ bd,
                            float* __restrict__ G, float* __restrict__ cur,
                            float* __restrict__ eD, float* __restrict__ eS,
                            float* __restrict__ rds,
                            float* __restrict__ deg, int* __restrict__ cnt) {
    __shared__ float sW[64 * 64];
    __shared__ float sb[64];
    __shared__ float sx[4][64];

    int gtid = blockIdx.x * 256 + threadIdx.x;
    if (gtid < 800000) deg[gtid] = 0.f;
    if (gtid < 400000) cnt[gtid] = 0;

    bool isDis = (blockIdx.x >= (DRUGN / 4));
    const float* W = isDis ? Wd : Wr;
    const float* b = isDis ? bd : br;
    for (int t = threadIdx.x; t < 4096; t += blockDim.x) sW[t] = W[t];
    if (threadIdx.x < 64) sb[threadIdx.x] = b[threadIdx.x];

    int local = threadIdx.x >> 6;             // 0..3
    int j     = threadIdx.x & 63;             // output column
    int n = blockIdx.x * 4 + local;           // node 0..NRD-1
    const float* emb = isDis ? se : de;
    size_t lrow = isDis ? (size_t)(n - DRUGN) * 64 : (size_t)n * 64;
    sx[local][j] = emb[lrow + j];
    __syncthreads();

    float z = sb[j];
#pragma unroll 16
    for (int k = 0; k < 64; k++) z = fmaf(sx[local][k], sW[k * 64 + j], z);
    float x = sx[local][j];
    float g = x * (1.0f / (1.0f + expf(-z)));

    size_t base = (size_t)n * 64;
    G[base + j]   = g;
    cur[base + j] = x;
    rds[(size_t)n * 256 + j] = x;
    if (!isDis) eD[base + j] = g;
    else        eS[(size_t)(n - DRUGN) * 64 + j] = g;
}

// ---------------- fused degree + row-histogram over ALL 3 graphs ----------------
__global__ void deghist_all(const int* __restrict__ rr_r, const int* __restrict__ rr_c, const float* __restrict__ rr_v,
                            const int* __restrict__ dd_r, const int* __restrict__ dd_c, const float* __restrict__ dd_v,
                            const int* __restrict__ rd_r, const int* __restrict__ rd_c, const float* __restrict__ rd_v,
                            float* __restrict__ deg, int* __restrict__ cnt) {
    int t = blockIdx.x * blockDim.x + threadIdx.x;
    if (t >= E_TOT) return;
    const int* er; const int* ec; const float* ev;
    int e; float* dr; float* dc; int* cn;
    if (t < EDG_RR) {
        e = t; er = rr_r; ec = rr_c; ev = rr_v;
        dr = deg + DRR_R; dc = deg + DRR_C; cn = cnt + CNT_RR;
    } else if (t < EDG_RR + EDG_DD) {
        e = t - EDG_RR; er = dd_r; ec = dd_c; ev = dd_v;
        dr = deg + DDD_R; dc = deg + DDD_C; cn = cnt + CNT_DD;
    } else {
        e = t - EDG_RR - EDG_DD; er = rd_r; ec = rd_c; ev = rd_v;
        dr = deg + DRD_R; dc = deg + DRD_C; cn = cnt + CNT_RD;
    }
    int r = er[e];
    float v = ev[e];
    atomicAdd(&dr[r], v);
    atomicAdd(&dc[ec[e]], v);
    atomicAdd(&cn[r], 1);
}

// ---------------- scan stage 1 ----------------
__global__ void scan1_kernel(const int* __restrict__ cnt, int* __restrict__ rptr,
                             int* __restrict__ bsum) {
    __shared__ int ts[1024];
    int t = threadIdx.x;
    int base = blockIdx.x * SCAN_BLK;
    int i0 = base + 2 * t, i1 = i0 + 1;
    int v0 = (i0 < SCAN_N) ? cnt[i0] : 0;
    int v1 = (i1 < SCAN_N) ? cnt[i1] : 0;
    ts[t] = v0 + v1;
    __syncthreads();
    for (int off = 1; off < 1024; off <<= 1) {
        int v = (t >= off) ? ts[t - off] : 0;
        __syncthreads();
        ts[t] += v;
        __syncthreads();
    }
    int excl = (t == 0) ? 0 : ts[t - 1];
    if (i0 < SCAN_N) rptr[i0] = excl;
    if (i1 < SCAN_N) rptr[i1] = excl + v0;
    if (t == 1023) bsum[blockIdx.x] = ts[1023];
}

// ---------------- scan stage 2+3 fused ----------------
__global__ void scan23_kernel(int* __restrict__ rptr, int* __restrict__ cursor,
                              const int* __restrict__ bsum) {
    __shared__ int ts[256];
    int t = threadIdx.x;
    ts[t] = (t < SCAN_NB) ? bsum[t] : 0;
    __syncthreads();
    for (int off = 1; off < 256; off <<= 1) {
        int v = (t >= off) ? ts[t - off] : 0;
        __syncthreads();
        ts[t] += v;
        __syncthreads();
    }
    int i = blockIdx.x * blockDim.x + threadIdx.x;
    if (i < SCAN_N) {
        int blk = i / SCAN_BLK;
        int off = (blk == 0) ? 0 : ts[blk - 1];
        int v = rptr[i] + off;
        rptr[i] = v;
        cursor[i] = v;
    } else if (i == SCAN_N) {
        rptr[i] = E_TOT;
        cursor[i] = E_TOT;
    }
}

// ---------------- fused CSR fill over ALL 3 graphs ----------------
__global__ void fill_all(const int* __restrict__ rr_r, const int* __restrict__ rr_c, const float* __restrict__ rr_v,
                         const int* __restrict__ dd_r, const int* __restrict__ dd_c, const float* __restrict__ dd_v,
                         const int* __restrict__ rd_r, const int* __restrict__ rd_c, const float* __restrict__ rd_v,
                         const float* __restrict__ deg, int* __restrict__ cursor,
                         int2* __restrict__ csr) {
    int t = blockIdx.x * blockDim.x + threadIdx.x;
    if (t >= E_TOT) return;
    const int* er; const int* ec; const float* ev;
    int e; const float* dr; const float* dc; int* cu;
    if (t < EDG_RR) {
        e = t; er = rr_r; ec = rr_c; ev = rr_v;
        dr = deg + DRR_R; dc = deg + DRR_C; cu = cursor + CNT_RR;
    } else if (t < EDG_RR + EDG_DD) {
        e = t - EDG_RR; er = dd_r; ec = dd_c; ev = dd_v;
        dr = deg + DDD_R; dc = deg + DDD_C; cu = cursor + CNT_DD;
    } else {
        e = t - EDG_RR - EDG_DD; er = rd_r; ec = rd_c; ev = rd_v;
        dr = deg + DRD_R; dc = deg + DRD_C; cu = cursor + CNT_RD;
    }
    int r = er[e], c = ec[e];
    float w = ev[e] * rsqrtf(fmaxf(dr[r] * dc[c], 1e-12f));
    int pos = atomicAdd(&cu[r], 1);
    int2 pk; pk.x = c; pk.y = __float_as_int(w);
    csr[pos] = pk;
}

// ---------------- CSR row gather (float2 per lane, 4-way unrolled) ----------------
// Identical accumulation structure/order to round 13 (rel_err stability).
__device__ __forceinline__ void accum_row(const int2* __restrict__ ep, int beg, int end,
                                          const float* __restrict__ src, int coff, int lane,
                                          float &o0, float &o1) {
    float a0 = 0.f, a1 = 0.f, b0 = 0.f, b1 = 0.f;
    int e = beg;
    for (; e + 3 < end; e += 4) {
        int2 p0 = ep[e], p1 = ep[e + 1], p2 = ep[e + 2], p3 = ep[e + 3];
        const float2* s0 = (const float2*)(src + (size_t)(p0.x + coff) * 64);
        const float2* s1 = (const float2*)(src + (size_t)(p1.x + coff) * 64);
        const float2* s2 = (const float2*)(src + (size_t)(p2.x + coff) * 64);
        const float2* s3 = (const float2*)(src + (size_t)(p3.x + coff) * 64);
        float2 v0 = s0[lane], v1 = s1[lane], v2 = s2[lane], v3 = s3[lane];
        float w0 = __int_as_float(p0.y), w1 = __int_as_float(p1.y);
        float w2 = __int_as_float(p2.y), w3 = __int_as_float(p3.y);
        a0 = fmaf(w0, v0.x, a0);  a1 = fmaf(w0, v0.y, a1);
        b0 = fmaf(w1, v1.x, b0);  b1 = fmaf(w1, v1.y, b1);
        a0 = fmaf(w2, v2.x, a0);  a1 = fmaf(w2, v2.y, a1);
        b0 = fmaf(w3, v3.x, b0);  b1 = fmaf(w3, v3.y, b1);
    }
    for (; e < end; e++) {
        int2 p = ep[e];
        float w = __int_as_float(p.y);
        const float2* s = (const float2*)(src + (size_t)(p.x + coff) * 64);
        float2 v = s[lane];
        a0 = fmaf(w, v.x, a0);    a1 = fmaf(w, v.y, a1);
    }
    o0 = a0 + b0; o1 = a1 + b1;
}

// ---------------- fused per-layer kernel, v2: warp-per-row gather ----------------
// Block = 256 threads = 8 warps = 2 pairs x 4 gather warps.
// Warp role r in {0:rr-n, 1:dd-m, 2:rd-n, 3:rd-m} gathers one row into shared.
// After barrier, role 0 combines the drug row, role 1 the dis row.
__global__ void layer_kernel(const int* __restrict__ rptr, const int2* __restrict__ csr,
                             const float* __restrict__ srcPD,  // G (layer0) or curA
                             const float* __restrict__ srcR,   // curA
                             float* __restrict__ curB,         // next cur (unused layer 2)
                             float* __restrict__ eD, float* __restrict__ eS,
                             float* __restrict__ rds,
                             int layer, uint32_t k0, uint32_t k1) {
    __shared__ float s[2][4][64];

    int warp = threadIdx.x >> 5;
    int lane = threadIdx.x & 31;
    int p    = warp >> 2;                 // pair slot in block: 0,1
    int role = warp & 3;                  // 0:rr-n 1:dd-m 2:rd-n 3:rd-m
    int gw   = blockIdx.x * 2 + p;        // drug index
    if (gw >= DRUGN) return;
    int m = gw + DRUGN;

    // ---- gather phase: one row per warp ----
    {
        int rbase, coff; const float* src;
        if (role == 0)      { rbase = CNT_RR + gw; coff = 0;     src = srcPD; }
        else if (role == 1) { rbase = CNT_DD + gw; coff = DRUGN; src = srcPD; }
        else if (role == 2) { rbase = CNT_RD + gw; coff = 0;     src = srcR;  }
        else                { rbase = CNT_RD + m;  coff = 0;     src = srcR;  }
        float o0, o1;
        accum_row(csr, rptr[rbase], rptr[rbase + 1], src, coff, lane, o0, o1);
        s[p][role][2 * lane]     = o0;
        s[p][role][2 * lane + 1] = o1;
    }
    __syncthreads();

    // ---- combine phase: role 0 -> drug row n, role 1 -> dis row m ----
    if (role < 2) {
        float p0 = s[p][role][2 * lane];
        float p1 = s[p][role][2 * lane + 1];
        float r0 = s[p][2 + role][2 * lane];
        float r1 = s[p][2 + role][2 * lane + 1];

        uint32_t f0 = (uint32_t)gw * 64u + 2u * (uint32_t)lane + (role ? HBITS : 0u);
        float u0 = u01(tf_bits32(k0, k1, f0));
        float u1 = u01(tf_bits32(k0, k1, f0 + 1u));

        float sn = fmaf(u0, u0, u1 * u1);
#pragma unroll
        for (int o = 16; o; o >>= 1) sn += __shfl_xor_sync(0xffffffffu, sn, o);
        float sc = EPSF / fmaxf(sqrtf(sn), 1e-12f);

        r0 += fsgn(r0) * u0 * sc;
        r1 += fsgn(r1) * u1 * sc;

        float qn = fmaf(r0, r0, r1 * r1);
#pragma unroll
        for (int o = 16; o; o >>= 1) qn += __shfl_xor_sync(0xffffffffu, qn, o);
        float inr = 1.f / fmaxf(sqrtf(qn), 1e-12f);

        int nodeIdx = role ? m : gw;
        // rds is 4-byte aligned only (odd base offset) -> SCALAR stores.
        size_t sb = (size_t)nodeIdx * 256 + (size_t)(layer + 1) * 64 + 2 * lane;
        rds[sb]     = r0 * inr;
        rds[sb + 1] = r1 * inr;

        if (layer < 2) {
            float2 wv;
            wv.x = 0.5f * p0 + 0.5f * r0;
            wv.y = 0.5f * p1 + 0.5f * r1;
            ((float2*)(curB + (size_t)nodeIdx * 64))[lane] = wv;
        }

        float tn = fmaf(p0, p0, p1 * p1);
#pragma unroll
        for (int o = 16; o; o >>= 1) tn += __shfl_xor_sync(0xffffffffu, tn, o);
        float ipn = 1.f / fmaxf(sqrtf(tn), 1e-12f);

        // drugE (role 0) / disE (role 1) both indexed by drug-row base gw*64
        float* eacc = role ? eS : eD;
        size_t bn = (size_t)gw * 64;
        float2 ev = ((float2*)(eacc + bn))[lane];
        ev.x += p0 * ipn;
        ev.y += p1 * ipn;
        ((float2*)(eacc + bn))[lane] = ev;
    }
}

// ---------------- final: scale means, combine with embeddings ----------------
__global__ void final_kernel(const float* __restrict__ de, const float* __restrict__ se,
                             float* __restrict__ out) {
    size_t i = (size_t)blockIdx.x * blockDim.x + threadIdx.x;
    if (i == 0) out[OFF_LOSS] = 0.f;
    if (i < 6400000) {
        float E = out[OFF_DRUGE + i] * 0.25f;
        float emb = de[i];
        out[OFF_DRUGE + i] = E;
        out[OFF_DRUGALL + i] = 0.5f * emb + 0.5f * E;
        out[OFF_RDDRUG + i] = emb;
    } else if (i < 12800000) {
        size_t j = i - 6400000;
        float E = out[OFF_DISE + j] * 0.25f;
        float emb = se[j];
        out[OFF_DISE + j] = E;
        out[OFF_DISALL + j] = 0.5f * emb + 0.5f * E;
        out[OFF_RDDIS + j] = emb;
    }
}

// ---------------- host-side threefry for key folding ----------------
static inline void tf_host(uint32_t k0, uint32_t k1, uint32_t* px0, uint32_t* px1) {
    uint32_t x0 = *px0, x1 = *px1;
    uint32_t k2 = k0 ^ k1 ^ 0x1BD11BDAu;
#define HROT(r) { x0 += x1; x1 = (x1 << r) | (x1 >> (32 - r)); x1 ^= x0; }
    x0 += k0; x1 += k1;
    HROT(13) HROT(15) HROT(26) HROT(6)
    x0 += k1; x1 += k2 + 1u;
    HROT(17) HROT(29) HROT(16) HROT(24)
    x0 += k2; x1 += k0 + 2u;
    HROT(13) HROT(15) HROT(26) HROT(6)
    x0 += k0; x1 += k1 + 3u;
    HROT(17) HROT(29) HROT(16) HROT(24)
    x0 += k1; x1 += k2 + 4u;
    HROT(13) HROT(15) HROT(26) HROT(6)
    x0 += k2; x1 += k0 + 5u;
#undef HROT
    *px0 = x0; *px1 = x1;
}

extern "C" void kernel_launch(void* const* d_in, const int* in_sizes, int n_in,
                              void* d_out, int out_size) {
    const float* drug_emb = (const float*)d_in[0];
    const float* dis_emb  = (const float*)d_in[1];
    const float* Wr = (const float*)d_in[2];
    const float* br = (const float*)d_in[3];
    const float* Wd = (const float*)d_in[4];
    const float* bd = (const float*)d_in[5];
    const int*   rr_row = (const int*)d_in[6];
    const int*   rr_col = (const int*)d_in[7];
    const float* rr_val = (const float*)d_in[8];
    const int*   dd_row = (const int*)d_in[9];
    const int*   dd_col = (const int*)d_in[10];
    const float* dd_val = (const float*)d_in[11];
    const int*   rd_row = (const int*)d_in[12];
    const int*   rd_col = (const int*)d_in[13];
    const float* rd_val = (const float*)d_in[14];
    float* out = (float*)d_out;

    float *G, *curA, *curB, *deg;
    int2 *csr; int *cnt, *rptr, *cursor, *bsum;
    cudaGetSymbolAddress((void**)&G,     g_G);
    cudaGetSymbolAddress((void**)&curA,  g_curA);
    cudaGetSymbolAddress((void**)&curB,  g_curB);
    cudaGetSymbolAddress((void**)&deg,   g_deg);
    cudaGetSymbolAddress((void**)&csr,   g_csr);
    cudaGetSymbolAddress((void**)&cnt,   g_cnt);
    cudaGetSymbolAddress((void**)&rptr,  g_rptr);
    cudaGetSymbolAddress((void**)&cursor,g_cursor);
    cudaGetSymbolAddress((void**)&bsum,  g_bsum);

    // Launch 0: init (gates, curA, rd_stack slice 0, eD/eS init) + zero deg/cnt
    init_kernel<<<NRD / 4, 256>>>(drug_emb, dis_emb, Wr, br, Wd, bd,
                                  G, curA, out + OFF_DRUGE, out + OFF_DISE,
                                  out + OFF_RDSTACK, deg, cnt);

    // Launch 1: degrees + row histogram (all graphs, one pass)
    deghist_all<<<(E_TOT + 255) / 256, 256>>>(rr_row, rr_col, rr_val,
                                              dd_row, dd_col, dd_val,
                                              rd_row, rd_col, rd_val, deg, cnt);

    // Launches 2-3: global exclusive scan of 400000 counts -> CSR offsets
    scan1_kernel<<<SCAN_NB, 1024>>>(cnt, rptr, bsum);
    scan23_kernel<<<(SCAN_N + 256) / 256, 256>>>(rptr, cursor, bsum);

    // Launch 4: CSR fill (all graphs, one pass)
    fill_all<<<(E_TOT + 255) / 256, 256>>>(rr_row, rr_col, rr_val,
                                           dd_row, dd_col, dd_val,
                                           rd_row, rd_col, rd_val,
                                           deg, cursor, csr);

    // Launches 5-7: fused layers (2 pairs per block, 4 gather warps per pair)
    float* bufs[2] = { curA, curB };
    for (int i = 0; i < 3; i++) {
        uint32_t lk0 = 0u, lk1 = (uint32_t)i;
        tf_host(0u, 1u, &lk0, &lk1);           // fold_in(key(1), i)
        const float* ca = bufs[i & 1];
        float*       cb = bufs[(i + 1) & 1];
        const float* srcPD = (i == 0) ? G : ca;
        layer_kernel<<<DRUGN / 2, 256>>>(rptr, csr, srcPD, ca, cb,
            out + OFF_DRUGE, out + OFF_DISE, out + OFF_RDSTACK, i, lk0, lk1);
    }

    // Launch 8: finalize outputs
    final_kernel<<<(12800000 + 255) / 256, 256>>>(drug_emb, dis_emb, out);
}